// round 15
// baseline (speedup 1.0000x reference)
#include <cuda_runtime.h>
#include <cuda_fp16.h>
#include <cstdint>
#include <cstddef>

typedef __half f16;

// ---------------- problem constants ----------------
#define TSTEPS 8
#define BATCH  64
#define CC     3
#define NWIN   232
#define HH     64
#define WW     64
#define CHUNK  29
#define DPP    13
#define INDIM  1024
#define H0     512
#define H1     512
#define H2     256
#define CD     39
#define FEAT   9984
#define NCLS   4
#define MROWS  (BATCH*CD)        // 2496
#define MALL   (TSTEPS*MROWS)    // 19968
#define BETA   0.9f
#define WSCALE 67108864.0f       // 2^26
#define WINV   (1.0f/67108864.0f)

// ---------------- scratch (static device memory) ----------------
__device__ f16   g_A0[(size_t)MALL * INDIM];
__device__ f16   g_A1[(size_t)MALL * INDIM];
__device__ float g_cur1[(size_t)MALL * H0];      // reused for cur2
__device__ float g_cur3[(size_t)MALL * H2];
__device__ __align__(16) char g_s1[(size_t)MALL * H0];
__device__ __align__(16) char g_s2[(size_t)MALL * H1];
__device__ __align__(16) char g_s3[(size_t)MALL * H2];
__device__ float g_curout[TSTEPS * BATCH * NCLS];
__device__ f16 g_Wi0[H0 * INDIM], g_Wi1[H0 * INDIM];
__device__ __align__(16) char g_D10[H1 * H0], g_D11[H1 * H0], g_D12[H1 * H0];
__device__ __align__(16) char g_D20[H2 * H1], g_D21[H2 * H1], g_D22[H2 * H1];

// ---------------- fp32 -> 2x fp16 split (24-bit capture) ----------------
__device__ __forceinline__ void split2(float a, f16& h0, f16& h1) {
    h0 = __float2half_rn(a);
    float r = a - __half2float(h0);    // exact (error-free transform)
    h1 = __float2half_rn(r);           // residual <= 2^-24 |a|
}

__global__ void wsplit_kernel(const float* __restrict__ w, int n,
                              f16* __restrict__ h0, f16* __restrict__ h1) {
    int i = blockIdx.x * blockDim.x + threadIdx.x;
    if (i >= n) return;
    f16 a, b;
    split2(w[i], a, b);
    h0[i] = a; h1[i] = b;
}

// fp32 -> 3 int8 digits (base 256): round(w*2^26) = (d0*256+d1)*256+d2 exactly
__global__ void wsplit_s8_kernel(const float* __restrict__ w, int n,
                                 char* __restrict__ d0, char* __restrict__ d1,
                                 char* __restrict__ d2) {
    int i = blockIdx.x * blockDim.x + threadIdx.x;
    if (i >= n) return;
    int v  = __float2int_rn(w[i] * WSCALE);   // |v| < 2^22 for |w| < 1/sqrt(512)
    int e2 = (v << 24) >> 24;                 // signed low byte
    int v1 = (v - e2) >> 8;                   // exact
    int e1 = (v1 << 24) >> 24;
    int e0 = (v1 - e1) >> 8;                  // |e0| <= 46
    d0[i] = (char)e0; d1[i] = (char)e1; d2[i] = (char)e2;
}

// ---------------- avg-pool3d fused with A-matrix 2-split ----------------
__global__ void pool_kernel(const float* __restrict__ x) {
    int idx = blockIdx.x * blockDim.x + threadIdx.x;
    if (idx >= MALL * INDIM) return;
    int hw = idx & (INDIM - 1);
    int r  = idx >> 10;
    int cd = r % CD;
    int tb = r / CD;
    int b  = tb % BATCH;
    int t  = tb / BATCH;
    int c  = cd / DPP;
    int dp = cd % DPP;
    int hp = hw >> 5;
    int wp = hw & 31;
    int d0 = t * CHUNK + 2 * dp;
    const float* base = x + (((size_t)b * CC + c) * NWIN) * (HH * WW)
                          + (size_t)(2 * hp) * WW + (size_t)(2 * wp);
    float s = 0.f;
#pragma unroll
    for (int kd = 0; kd < 4; kd++) {
        const float* p = base + (size_t)(d0 + kd) * (HH * WW);
        float2 r0 = *(const float2*)(p);
        float2 r1 = *(const float2*)(p + WW);
        s += (r0.x + r0.y) + (r1.x + r1.y);
    }
    s *= (1.0f / 16.0f);
    f16 h0, h1;
    split2(s, h0, h1);
    g_A0[idx] = h0; g_A1[idx] = h1;
}

// ---------------- cp.async / ldmatrix helpers ----------------
__device__ __forceinline__ void cpasync16(void* s, const void* g) {
    uint32_t sa = (uint32_t)__cvta_generic_to_shared(s);
    asm volatile("cp.async.cg.shared.global [%0], [%1], 16;\n" :: "r"(sa), "l"(g));
}
__device__ __forceinline__ void cp_commit() {
    asm volatile("cp.async.commit_group;\n");
}
template<int N> __device__ __forceinline__ void cp_wait() {
    asm volatile("cp.async.wait_group %0;\n" :: "n"(N));
}
__device__ __forceinline__ void ldmatrix_x4(uint32_t* r, const void* p) {
    uint32_t a = (uint32_t)__cvta_generic_to_shared(p);
    asm volatile("ldmatrix.sync.aligned.m8n8.x4.shared.b16 {%0,%1,%2,%3}, [%4];\n"
        : "=r"(r[0]), "=r"(r[1]), "=r"(r[2]), "=r"(r[3]) : "r"(a));
}

// ---------------- MMA primitives ----------------
__device__ __forceinline__ void mma16816(float* c, const uint32_t* a, const uint32_t* b) {
    asm volatile(
        "mma.sync.aligned.m16n8k16.row.col.f32.f16.f16.f32 "
        "{%0,%1,%2,%3},{%4,%5,%6,%7},{%8,%9},{%0,%1,%2,%3};\n"
        : "+f"(c[0]), "+f"(c[1]), "+f"(c[2]), "+f"(c[3])
        : "r"(a[0]), "r"(a[1]), "r"(a[2]), "r"(a[3]), "r"(b[0]), "r"(b[1]));
}
__device__ __forceinline__ void mma16832s8(int32_t* c, const uint32_t* a, const uint32_t* b) {
    asm volatile(
        "mma.sync.aligned.m16n8k32.row.col.s32.s8.s8.s32 "
        "{%0,%1,%2,%3},{%4,%5,%6,%7},{%8,%9},{%0,%1,%2,%3};\n"
        : "+r"(c[0]), "+r"(c[1]), "+r"(c[2]), "+r"(c[3])
        : "r"(a[0]), "r"(a[1]), "r"(a[2]), "r"(a[3]), "r"(b[0]), "r"(b[1]));
}

// ---------------- fp16 multi-term GEMM (fc1), 3-stage pipeline ------------
struct Terms {
    const f16* A[3];
    const f16* B[3];
};

template<int NT, int K>
__global__ void __launch_bounds__(128, 2)
mma_gemm(Terms terms, const float* __restrict__ bias,
         float* __restrict__ curOut, int N) {
    constexpr int BM = 128, BN = 128, BK = 64;
    constexpr int WM = 64,  WN = 64;
    constexpr int PAD = 8, LDW = BK + PAD;
    constexpr int STAGES = 3;
    constexpr int KT = K / BK;
    constexpr int NTILE = NT * KT;
    constexpr int MF = WM / 16, NF = WN / 8;   // 4, 8

    extern __shared__ char dynsmem[];
    f16 (*As)[BM][LDW] = (f16(*)[BM][LDW])dynsmem;
    f16 (*Bs)[BN][LDW] = (f16(*)[BN][LDW])(dynsmem + (size_t)STAGES * BM * LDW * 2);

    const int tid  = threadIdx.x;
    const int lane = tid & 31;
    const int warp = tid >> 5;
    const int g    = lane >> 2;
    const int tg   = lane & 3;
    const int wn0  = (warp & 1) * WN;
    const int wm0  = (warp >> 1) * WM;
    const int bm   = blockIdx.y * BM;
    const int bn   = blockIdx.x * BN;

    const int l8   = lane & 7;
    const int aRow = ((lane >> 3) & 1) * 8 + l8;
    const int aCol = (lane >> 4) * 8;
    const int bRow = (lane >> 4) * 8 + l8;
    const int bCol = ((lane >> 3) & 1) * 8;

    const int lr = tid >> 3;
    const int lc = (tid & 7) * 8;

    auto load_tile = [&](int i, int s) {
        const int term = i / KT;
        const int k0   = (i % KT) * BK;
        const f16* __restrict__ Ag = terms.A[term] + (size_t)bm * K + k0;
        const f16* __restrict__ Bg = terms.B[term] + (size_t)bn * K + k0;
#pragma unroll
        for (int it = 0; it < 8; it++)
            cpasync16(&As[s][lr + it*16][lc], Ag + (size_t)(lr + it*16) * K + lc);
#pragma unroll
        for (int it = 0; it < 8; it++)
            cpasync16(&Bs[s][lr + it*16][lc], Bg + (size_t)(lr + it*16) * K + lc);
        cp_commit();
    };

    float acc[MF][NF][4];
#pragma unroll
    for (int i = 0; i < MF; i++)
#pragma unroll
        for (int j = 0; j < NF; j++)
#pragma unroll
            for (int q = 0; q < 4; q++) acc[i][j][q] = 0.f;

#pragma unroll
    for (int i = 0; i < STAGES - 1; i++) load_tile(i, i);

    for (int i = 0; i < NTILE; i++) {
        cp_wait<STAGES - 2>();
        __syncthreads();
        const int nxt = i + STAGES - 1;
        if (nxt < NTILE) load_tile(nxt, nxt % STAGES);
        const int st = i % STAGES;
#pragma unroll
        for (int ks = 0; ks < BK; ks += 16) {
            uint32_t fa[MF][4], fb[NF][2];
#pragma unroll
            for (int mf = 0; mf < MF; mf++)
                ldmatrix_x4(fa[mf], &As[st][wm0 + mf*16 + aRow][ks + aCol]);
#pragma unroll
            for (int p = 0; p < NF/2; p++) {
                uint32_t r[4];
                ldmatrix_x4(r, &Bs[st][wn0 + p*16 + bRow][ks + bCol]);
                fb[2*p  ][0] = r[0]; fb[2*p  ][1] = r[1];
                fb[2*p+1][0] = r[2]; fb[2*p+1][1] = r[3];
            }
#pragma unroll
            for (int mf = 0; mf < MF; mf++)
#pragma unroll
                for (int nf = 0; nf < NF; nf++)
                    mma16816(acc[mf][nf], fa[mf], fb[nf]);
        }
    }

#pragma unroll
    for (int mf = 0; mf < MF; mf++) {
#pragma unroll
        for (int nf = 0; nf < NF; nf++) {
            int m0 = bm + wm0 + mf*16 + g;
            int n0 = bn + wn0 + nf*8 + 2*tg;
#pragma unroll
            for (int q = 0; q < 4; q++) {
                int m = m0 + (q >> 1) * 8;
                int n = n0 + (q & 1);
                curOut[(size_t)m * N + n] = acc[mf][nf][q] + bias[n];
            }
        }
    }
}

// ---------------- int8 3-digit GEMM (fc2/fc3): exact integer accumulation --
// A = spikes {0,1} int8, B = digit matrices d0,d1,d2. Term-major tile loop;
// acc <<= 8 at digit boundaries reassembles round(w*2^26) dot products exactly.
// Smem / ldmatrix addressing identical to fp16 kernel via b16-view of int8 pairs.
struct TermsS8 {
    const f16* A[3];   // reinterpreted int8 (pairs as b16)
    const f16* B[3];
};

template<int K16>      // K in b16 units = K_int8/2
__global__ void __launch_bounds__(128, 2)
mma_gemm_s8(TermsS8 terms, const float* __restrict__ bias,
            float* __restrict__ curOut, int N) {
    constexpr int NT = 3;
    constexpr int BM = 128, BN = 128, BK = 64;   // BK in b16 units = 128 int8 k
    constexpr int WM = 64,  WN = 64;
    constexpr int PAD = 8, LDW = BK + PAD;
    constexpr int STAGES = 3;
    constexpr int KT = K16 / BK;
    constexpr int NTILE = NT * KT;
    constexpr int MF = WM / 16, NF = WN / 8;

    extern __shared__ char dynsmem[];
    f16 (*As)[BM][LDW] = (f16(*)[BM][LDW])dynsmem;
    f16 (*Bs)[BN][LDW] = (f16(*)[BN][LDW])(dynsmem + (size_t)STAGES * BM * LDW * 2);

    const int tid  = threadIdx.x;
    const int lane = tid & 31;
    const int warp = tid >> 5;
    const int g    = lane >> 2;
    const int tg   = lane & 3;
    const int wn0  = (warp & 1) * WN;
    const int wm0  = (warp >> 1) * WM;
    const int bm   = blockIdx.y * BM;
    const int bn   = blockIdx.x * BN;

    const int l8   = lane & 7;
    const int aRow = ((lane >> 3) & 1) * 8 + l8;
    const int aCol = (lane >> 4) * 8;
    const int bRow = (lane >> 4) * 8 + l8;
    const int bCol = ((lane >> 3) & 1) * 8;

    const int lr = tid >> 3;
    const int lc = (tid & 7) * 8;

    auto load_tile = [&](int i, int s) {
        const int term = i / KT;
        const int k0   = (i % KT) * BK;
        const f16* __restrict__ Ag = terms.A[term] + (size_t)bm * K16 + k0;
        const f16* __restrict__ Bg = terms.B[term] + (size_t)bn * K16 + k0;
#pragma unroll
        for (int it = 0; it < 8; it++)
            cpasync16(&As[s][lr + it*16][lc], Ag + (size_t)(lr + it*16) * K16 + lc);
#pragma unroll
        for (int it = 0; it < 8; it++)
            cpasync16(&Bs[s][lr + it*16][lc], Bg + (size_t)(lr + it*16) * K16 + lc);
        cp_commit();
    };

    int32_t acc[MF][NF][4];
#pragma unroll
    for (int i = 0; i < MF; i++)
#pragma unroll
        for (int j = 0; j < NF; j++)
#pragma unroll
            for (int q = 0; q < 4; q++) acc[i][j][q] = 0;

#pragma unroll
    for (int i = 0; i < STAGES - 1; i++) load_tile(i, i);

    for (int i = 0; i < NTILE; i++) {
        cp_wait<STAGES - 2>();
        __syncthreads();
        const int nxt = i + STAGES - 1;
        if (nxt < NTILE) load_tile(nxt, nxt % STAGES);
        const int st = i % STAGES;
#pragma unroll
        for (int ks = 0; ks < BK; ks += 16) {
            uint32_t fa[MF][4], fb[NF][2];
#pragma unroll
            for (int mf = 0; mf < MF; mf++)
                ldmatrix_x4(fa[mf], &As[st][wm0 + mf*16 + aRow][ks + aCol]);
#pragma unroll
            for (int p = 0; p < NF/2; p++) {
                uint32_t r[4];
                ldmatrix_x4(r, &Bs[st][wn0 + p*16 + bRow][ks + bCol]);
                fb[2*p  ][0] = r[0]; fb[2*p  ][1] = r[1];
                fb[2*p+1][0] = r[2]; fb[2*p+1][1] = r[3];
            }
#pragma unroll
            for (int mf = 0; mf < MF; mf++)
#pragma unroll
                for (int nf = 0; nf < NF; nf++)
                    mma16832s8(acc[mf][nf], fa[mf], fb[nf]);
        }
        // digit boundary: shift accumulated sum up one base-256 digit
        if (((i + 1) % KT == 0) && (i + 1) < NTILE) {
#pragma unroll
            for (int mf = 0; mf < MF; mf++)
#pragma unroll
                for (int nf = 0; nf < NF; nf++)
#pragma unroll
                    for (int q = 0; q < 4; q++) acc[mf][nf][q] <<= 8;
        }
    }

#pragma unroll
    for (int mf = 0; mf < MF; mf++) {
#pragma unroll
        for (int nf = 0; nf < NF; nf++) {
            int m0 = bm + wm0 + mf*16 + g;
            int n0 = bn + wn0 + nf*8 + 2*tg;
#pragma unroll
            for (int q = 0; q < 4; q++) {
                int m = m0 + (q >> 1) * 8;
                int n = n0 + (q & 1);
                curOut[(size_t)m * N + n] = (float)acc[mf][nf][q] * WINV + bias[n];
            }
        }
    }
}

// ---------------- LIF time-scan: membrane in register, int8 spikes --------
__global__ void lif_scan_kernel(const float* __restrict__ cur,
                                char* __restrict__ spk, int n, float thr) {
    int i = blockIdx.x * blockDim.x + threadIdx.x;
    if (i >= n) return;
    float m = 0.f;
#pragma unroll
    for (int t = 0; t < TSTEPS; t++) {
        float reset = (m > thr) ? thr : 0.f;
        m = BETA * m + cur[(size_t)t * n + i] - reset;
        spk[(size_t)t * n + i] = (char)((m - thr) > 0.f ? 1 : 0);
    }
}

// layer-1 variant writing fp16 spikes (fc2 input is... fc2 A is int8 now)
__global__ void lif_scan_f16_unused() {}

// ---------------- readout currents: (t,b) row x Wout (4 x 9984) ----------
__global__ void fcout_kernel(const char* __restrict__ s3,
                             const float* __restrict__ Wout,
                             const float* __restrict__ bout,
                             float* __restrict__ curout) {
    const int tb  = blockIdx.x;          // t*BATCH + b
    const int t   = tb / BATCH;
    const int b   = tb % BATCH;
    const int tid = threadIdx.x;         // 256
    const char* sp = s3 + ((size_t)t * MROWS + (size_t)b * CD) * H2;
    float a0 = 0.f, a1 = 0.f, a2 = 0.f, a3 = 0.f;
    for (int k = tid; k < FEAT; k += 256) {
        if (sp[k]) {
            a0 += Wout[0 * FEAT + k];
            a1 += Wout[1 * FEAT + k];
            a2 += Wout[2 * FEAT + k];
            a3 += Wout[3 * FEAT + k];
        }
    }
    __shared__ float red[4][256];
    red[0][tid] = a0; red[1][tid] = a1; red[2][tid] = a2; red[3][tid] = a3;
    __syncthreads();
    for (int st = 128; st > 0; st >>= 1) {
        if (tid < st) {
#pragma unroll
            for (int n = 0; n < 4; n++) red[n][tid] += red[n][tid + st];
        }
        __syncthreads();
    }
    if (tid < NCLS)
        curout[(size_t)tb * NCLS + tid] = red[tid][0] + bout[tid];
}

// ---------------- output LIF scan (thr = 1.0) ----------------------------
__global__ void lifout_kernel(const float* __restrict__ curout,
                              float* __restrict__ out) {
    int i = threadIdx.x;                 // BATCH*NCLS = 256
    float m = 0.f;
#pragma unroll
    for (int t = 0; t < TSTEPS; t++) {
        float reset = (m > 1.0f) ? 1.0f : 0.f;
        m = BETA * m + curout[t * BATCH * NCLS + i] - reset;
        out[t * BATCH * NCLS + i] = (m - 1.0f) > 0.f ? 1.f : 0.f;
    }
}

// ---------------- host orchestration (single stream, no allocations) ------
extern "C" void kernel_launch(void* const* d_in, const int* in_sizes, int n_in,
                              void* d_out, int out_size) {
    const float* x     = (const float*)d_in[0];
    const float* W_in  = (const float*)d_in[1];
    const float* b_in  = (const float*)d_in[2];
    const float* W_h1  = (const float*)d_in[3];
    const float* b_h1  = (const float*)d_in[4];
    const float* W_h2  = (const float*)d_in[5];
    const float* b_h2  = (const float*)d_in[6];
    const float* W_out = (const float*)d_in[7];
    const float* b_out = (const float*)d_in[8];
    float* out = (float*)d_out;

    f16 *A0, *A1, *Wi0, *Wi1;
    char *s1, *s2, *s3, *D10, *D11, *D12, *D20, *D21, *D22;
    float *cur12, *cur3, *curout;
    cudaGetSymbolAddress((void**)&A0, g_A0);
    cudaGetSymbolAddress((void**)&A1, g_A1);
    cudaGetSymbolAddress((void**)&cur12, g_cur1);
    cudaGetSymbolAddress((void**)&cur3, g_cur3);
    cudaGetSymbolAddress((void**)&curout, g_curout);
    cudaGetSymbolAddress((void**)&s1, g_s1);
    cudaGetSymbolAddress((void**)&s2, g_s2);
    cudaGetSymbolAddress((void**)&s3, g_s3);
    cudaGetSymbolAddress((void**)&Wi0, g_Wi0);
    cudaGetSymbolAddress((void**)&Wi1, g_Wi1);
    cudaGetSymbolAddress((void**)&D10, g_D10);
    cudaGetSymbolAddress((void**)&D11, g_D11);
    cudaGetSymbolAddress((void**)&D12, g_D12);
    cudaGetSymbolAddress((void**)&D20, g_D20);
    cudaGetSymbolAddress((void**)&D21, g_D21);
    cudaGetSymbolAddress((void**)&D22, g_D22);

    constexpr int SMEM = 3 * (128 + 128) * 72 * 2;   // 110592
    auto kfc1 = mma_gemm<3, 1024>;
    auto kfcs8 = mma_gemm_s8<256>;                   // K=512 int8 = 256 b16 units
    cudaFuncSetAttribute(kfc1,  cudaFuncAttributeMaxDynamicSharedMemorySize, SMEM);
    cudaFuncSetAttribute(kfcs8, cudaFuncAttributeMaxDynamicSharedMemorySize, SMEM);

    // weight prep
    wsplit_kernel<<<(H0*INDIM + 255)/256, 256>>>(W_in, H0*INDIM, Wi0, Wi1);
    wsplit_s8_kernel<<<(H1*H0 + 255)/256, 256>>>(W_h1, H1*H0, D10, D11, D12);
    wsplit_s8_kernel<<<(H2*H1 + 255)/256, 256>>>(W_h2, H2*H1, D20, D21, D22);

    pool_kernel<<<(MALL*INDIM + 255)/256, 256>>>(x);

    // fc1: 3-term fp16 split GEMM (19968x1024 -> 512)
    {
        Terms t1;
        t1.A[0]=A0; t1.B[0]=Wi0;
        t1.A[1]=A0; t1.B[1]=Wi1;
        t1.A[2]=A1; t1.B[2]=Wi0;
        kfc1<<<dim3(H0/128, MALL/128), 128, SMEM>>>(t1, b_in, cur12, H0);
    }
    lif_scan_kernel<<<(MROWS*H0 + 255)/256, 256>>>(cur12, s1, MROWS*H0, 0.5f);

    // fc2: int8 3-digit exact GEMM (19968x512 -> 512)
    {
        TermsS8 t2;
        t2.A[0] = t2.A[1] = t2.A[2] = (const f16*)s1;
        t2.B[0] = (const f16*)D10;
        t2.B[1] = (const f16*)D11;
        t2.B[2] = (const f16*)D12;
        kfcs8<<<dim3(H1/128, MALL/128), 128, SMEM>>>(t2, b_h1, cur12, H1);
    }
    lif_scan_kernel<<<(MROWS*H1 + 255)/256, 256>>>(cur12, s2, MROWS*H1, 0.5f);

    // fc3: int8 3-digit exact GEMM (19968x512 -> 256)
    {
        TermsS8 t3;
        t3.A[0] = t3.A[1] = t3.A[2] = (const f16*)s2;
        t3.B[0] = (const f16*)D20;
        t3.B[1] = (const f16*)D21;
        t3.B[2] = (const f16*)D22;
        kfcs8<<<dim3(H2/128, MALL/128), 128, SMEM>>>(t3, b_h2, cur3, H2);
    }
    lif_scan_kernel<<<(MROWS*H2 + 255)/256, 256>>>(cur3, s3, MROWS*H2, 0.5f);

    fcout_kernel<<<TSTEPS*BATCH, 256>>>(s3, W_out, b_out, curout);
    lifout_kernel<<<1, BATCH*NCLS>>>(curout, out);
}

// round 16
// speedup vs baseline: 1.5986x; 1.5986x over previous
#include <cuda_runtime.h>
#include <cuda_fp16.h>
#include <cstdint>
#include <cstddef>

typedef __half f16;

// ---------------- problem constants ----------------
#define TSTEPS 8
#define BATCH  64
#define CC     3
#define NWIN   232
#define HH     64
#define WW     64
#define CHUNK  29
#define DPP    13
#define INDIM  1024
#define H0     512
#define H1     512
#define H2     256
#define CD     39
#define FEAT   9984
#define NCLS   4
#define MROWS  (BATCH*CD)        // 2496
#define MALL   (TSTEPS*MROWS)    // 19968
#define BETA   0.9f

// ---------------- scratch (static device memory) ----------------
__device__ f16   g_A0[(size_t)MALL * INDIM];
__device__ f16   g_A1[(size_t)MALL * INDIM];
__device__ float g_cur1[(size_t)MALL * H0];      // reused for cur2
__device__ float g_cur3[(size_t)MALL * H2];
__device__ f16   g_s1[(size_t)MALL * H0];
__device__ f16   g_s2[(size_t)MALL * H1];
__device__ f16   g_s3[(size_t)MALL * H2];
__device__ float g_curout[TSTEPS * BATCH * NCLS];
__device__ f16 g_Wi0[H0 * INDIM], g_Wi1[H0 * INDIM];
__device__ f16 g_W10[H1 * H0],    g_W11[H1 * H0];
__device__ f16 g_W20[H2 * H1],    g_W21[H2 * H1];

// ---------------- fp32 -> 2x fp16 split (24-bit capture) ----------------
__device__ __forceinline__ void split2(float a, f16& h0, f16& h1) {
    h0 = __float2half_rn(a);
    float r = a - __half2float(h0);    // exact (error-free transform)
    h1 = __float2half_rn(r);           // residual <= 2^-24 |a|
}

__global__ void wsplit_kernel(const float* __restrict__ w, int n,
                              f16* __restrict__ h0, f16* __restrict__ h1) {
    int i = blockIdx.x * blockDim.x + threadIdx.x;
    if (i >= n) return;
    f16 a, b;
    split2(w[i], a, b);
    h0[i] = a; h1[i] = b;
}

// ---------------- avg-pool3d fused with A-matrix 2-split ----------------
__global__ void pool_kernel(const float* __restrict__ x) {
    int idx = blockIdx.x * blockDim.x + threadIdx.x;
    if (idx >= MALL * INDIM) return;
    int hw = idx & (INDIM - 1);
    int r  = idx >> 10;
    int cd = r % CD;
    int tb = r / CD;
    int b  = tb % BATCH;
    int t  = tb / BATCH;
    int c  = cd / DPP;
    int dp = cd % DPP;
    int hp = hw >> 5;
    int wp = hw & 31;
    int d0 = t * CHUNK + 2 * dp;
    const float* base = x + (((size_t)b * CC + c) * NWIN) * (HH * WW)
                          + (size_t)(2 * hp) * WW + (size_t)(2 * wp);
    float s = 0.f;
#pragma unroll
    for (int kd = 0; kd < 4; kd++) {
        const float* p = base + (size_t)(d0 + kd) * (HH * WW);
        float2 r0 = *(const float2*)(p);
        float2 r1 = *(const float2*)(p + WW);
        s += (r0.x + r0.y) + (r1.x + r1.y);
    }
    s *= (1.0f / 16.0f);
    f16 h0, h1;
    split2(s, h0, h1);
    g_A0[idx] = h0; g_A1[idx] = h1;
}

// ---------------- cp.async / ldmatrix helpers ----------------
__device__ __forceinline__ void cpasync16(void* s, const void* g) {
    uint32_t sa = (uint32_t)__cvta_generic_to_shared(s);
    asm volatile("cp.async.cg.shared.global [%0], [%1], 16;\n" :: "r"(sa), "l"(g));
}
__device__ __forceinline__ void cp_commit() {
    asm volatile("cp.async.commit_group;\n");
}
template<int N> __device__ __forceinline__ void cp_wait() {
    asm volatile("cp.async.wait_group %0;\n" :: "n"(N));
}
__device__ __forceinline__ void ldmatrix_x4(uint32_t* r, const void* p) {
    uint32_t a = (uint32_t)__cvta_generic_to_shared(p);
    asm volatile("ldmatrix.sync.aligned.m8n8.x4.shared.b16 {%0,%1,%2,%3}, [%4];\n"
        : "=r"(r[0]), "=r"(r[1]), "=r"(r[2]), "=r"(r[3]) : "r"(a));
}

// ---------------- fp16 tensor-core multi-term GEMM, 3-stage pipeline ------
struct Terms {
    const f16* A[3];
    const f16* B[3];
};

__device__ __forceinline__ void mma16816(float* c, const uint32_t* a, const uint32_t* b) {
    asm volatile(
        "mma.sync.aligned.m16n8k16.row.col.f32.f16.f16.f32 "
        "{%0,%1,%2,%3},{%4,%5,%6,%7},{%8,%9},{%0,%1,%2,%3};\n"
        : "+f"(c[0]), "+f"(c[1]), "+f"(c[2]), "+f"(c[3])
        : "r"(a[0]), "r"(a[1]), "r"(a[2]), "r"(a[3]), "r"(b[0]), "r"(b[1]));
}

// BM=128, BN=64, BK=64, 4 warps (warp tile 64x32), 3-stage cp.async, 2 CTAs/SM.
// Finer N tiling -> 1248-block grids -> 84% wave utilization on 296 CTA slots.
template<int NT, int K>
__global__ void __launch_bounds__(128, 2)
mma_gemm(Terms terms, const float* __restrict__ bias,
         float* __restrict__ curOut, int N) {
    constexpr int BM = 128, BN = 64, BK = 64;
    constexpr int WM = 64,  WN = 32;
    constexpr int PAD = 8, LDW = BK + PAD;
    constexpr int STAGES = 3;
    constexpr int KT = K / BK;
    constexpr int NTILE = NT * KT;
    constexpr int MF = WM / 16, NF = WN / 8;   // 4, 4

    extern __shared__ char dynsmem[];
    f16 (*As)[BM][LDW] = (f16(*)[BM][LDW])dynsmem;
    f16 (*Bs)[BN][LDW] = (f16(*)[BN][LDW])(dynsmem + (size_t)STAGES * BM * LDW * 2);

    const int tid  = threadIdx.x;
    const int lane = tid & 31;
    const int warp = tid >> 5;
    const int g    = lane >> 2;
    const int tg   = lane & 3;
    const int wn0  = (warp & 1) * WN;
    const int wm0  = (warp >> 1) * WM;
    const int bm   = blockIdx.y * BM;
    const int bn   = blockIdx.x * BN;

    const int l8   = lane & 7;
    const int aRow = ((lane >> 3) & 1) * 8 + l8;
    const int aCol = (lane >> 4) * 8;
    const int bRow = (lane >> 4) * 8 + l8;
    const int bCol = ((lane >> 3) & 1) * 8;

    // loader: BK=64 -> 8 x 16B chunks per row; 128 threads -> 16 rows/pass
    const int lr = tid >> 3;
    const int lc = (tid & 7) * 8;

    auto load_tile = [&](int i, int s) {
        const int term = i / KT;
        const int k0   = (i % KT) * BK;
        const f16* __restrict__ Ag = terms.A[term] + (size_t)bm * K + k0;
        const f16* __restrict__ Bg = terms.B[term] + (size_t)bn * K + k0;
#pragma unroll
        for (int it = 0; it < BM/16; it++)
            cpasync16(&As[s][lr + it*16][lc], Ag + (size_t)(lr + it*16) * K + lc);
#pragma unroll
        for (int it = 0; it < BN/16; it++)
            cpasync16(&Bs[s][lr + it*16][lc], Bg + (size_t)(lr + it*16) * K + lc);
        cp_commit();
    };

    float acc[MF][NF][4];
#pragma unroll
    for (int i = 0; i < MF; i++)
#pragma unroll
        for (int j = 0; j < NF; j++)
#pragma unroll
            for (int q = 0; q < 4; q++) acc[i][j][q] = 0.f;

#pragma unroll
    for (int i = 0; i < STAGES - 1; i++) load_tile(i, i);

    for (int i = 0; i < NTILE; i++) {
        cp_wait<STAGES - 2>();
        __syncthreads();
        const int nxt = i + STAGES - 1;
        if (nxt < NTILE) load_tile(nxt, nxt % STAGES);
        const int st = i % STAGES;
#pragma unroll
        for (int ks = 0; ks < BK; ks += 16) {
            uint32_t fa[MF][4], fb[NF][2];
#pragma unroll
            for (int mf = 0; mf < MF; mf++)
                ldmatrix_x4(fa[mf], &As[st][wm0 + mf*16 + aRow][ks + aCol]);
#pragma unroll
            for (int p = 0; p < NF/2; p++) {
                uint32_t r[4];
                ldmatrix_x4(r, &Bs[st][wn0 + p*16 + bRow][ks + bCol]);
                fb[2*p  ][0] = r[0]; fb[2*p  ][1] = r[1];
                fb[2*p+1][0] = r[2]; fb[2*p+1][1] = r[3];
            }
#pragma unroll
            for (int mf = 0; mf < MF; mf++)
#pragma unroll
                for (int nf = 0; nf < NF; nf++)
                    mma16816(acc[mf][nf], fa[mf], fb[nf]);
        }
    }

    // epilogue: fp32 currents + bias
#pragma unroll
    for (int mf = 0; mf < MF; mf++) {
#pragma unroll
        for (int nf = 0; nf < NF; nf++) {
            int m0 = bm + wm0 + mf*16 + g;
            int n0 = bn + wn0 + nf*8 + 2*tg;
#pragma unroll
            for (int q = 0; q < 4; q++) {
                int m = m0 + (q >> 1) * 8;
                int n = n0 + (q & 1);
                curOut[(size_t)m * N + n] = acc[mf][nf][q] + bias[n];
            }
        }
    }
}

// ---------------- LIF time-scan: membrane in register, vectorized x4 ------
// n must be divisible by 4 (H0/H1/H2 * MROWS all are).
__global__ void lif_scan_kernel(const float* __restrict__ cur,
                                f16* __restrict__ spk, int n, float thr) {
    int i = (blockIdx.x * blockDim.x + threadIdx.x) * 4;
    if (i >= n) return;
    float4 m = make_float4(0.f, 0.f, 0.f, 0.f);
#pragma unroll
    for (int t = 0; t < TSTEPS; t++) {
        float4 c = *(const float4*)(cur + (size_t)t * n + i);
        m.x = BETA * m.x + c.x - ((m.x > thr) ? thr : 0.f);
        m.y = BETA * m.y + c.y - ((m.y > thr) ? thr : 0.f);
        m.z = BETA * m.z + c.z - ((m.z > thr) ? thr : 0.f);
        m.w = BETA * m.w + c.w - ((m.w > thr) ? thr : 0.f);
        __half2 lo = __halves2half2(__float2half_rn((m.x - thr) > 0.f ? 1.f : 0.f),
                                    __float2half_rn((m.y - thr) > 0.f ? 1.f : 0.f));
        __half2 hi = __halves2half2(__float2half_rn((m.z - thr) > 0.f ? 1.f : 0.f),
                                    __float2half_rn((m.w - thr) > 0.f ? 1.f : 0.f));
        *(uint2*)(spk + (size_t)t * n + i) =
            make_uint2(*(uint32_t*)&lo, *(uint32_t*)&hi);
    }
}

// ---------------- readout currents: (t,b) row x Wout (4 x 9984) ----------
__global__ void fcout_kernel(const f16* __restrict__ s3,
                             const float* __restrict__ Wout,
                             const float* __restrict__ bout,
                             float* __restrict__ curout) {
    const int tb  = blockIdx.x;          // t*BATCH + b
    const int t   = tb / BATCH;
    const int b   = tb % BATCH;
    const int tid = threadIdx.x;         // 256
    const f16* sp = s3 + ((size_t)t * MROWS + (size_t)b * CD) * H2;
    float a0 = 0.f, a1 = 0.f, a2 = 0.f, a3 = 0.f;
    for (int k = tid; k < FEAT; k += 256) {
        if (__half2float(sp[k]) != 0.f) {
            a0 += Wout[0 * FEAT + k];
            a1 += Wout[1 * FEAT + k];
            a2 += Wout[2 * FEAT + k];
            a3 += Wout[3 * FEAT + k];
        }
    }
    __shared__ float red[4][256];
    red[0][tid] = a0; red[1][tid] = a1; red[2][tid] = a2; red[3][tid] = a3;
    __syncthreads();
    for (int st = 128; st > 0; st >>= 1) {
        if (tid < st) {
#pragma unroll
            for (int n = 0; n < 4; n++) red[n][tid] += red[n][tid + st];
        }
        __syncthreads();
    }
    if (tid < NCLS)
        curout[(size_t)tb * NCLS + tid] = red[tid][0] + bout[tid];
}

// ---------------- output LIF scan (thr = 1.0) ----------------------------
__global__ void lifout_kernel(const float* __restrict__ curout,
                              float* __restrict__ out) {
    int i = threadIdx.x;                 // BATCH*NCLS = 256
    float m = 0.f;
#pragma unroll
    for (int t = 0; t < TSTEPS; t++) {
        float reset = (m > 1.0f) ? 1.0f : 0.f;
        m = BETA * m + curout[t * BATCH * NCLS + i] - reset;
        out[t * BATCH * NCLS + i] = (m - 1.0f) > 0.f ? 1.f : 0.f;
    }
}

// ---------------- host orchestration (single stream) ----------------------
extern "C" void kernel_launch(void* const* d_in, const int* in_sizes, int n_in,
                              void* d_out, int out_size) {
    const float* x     = (const float*)d_in[0];
    const float* W_in  = (const float*)d_in[1];
    const float* b_in  = (const float*)d_in[2];
    const float* W_h1  = (const float*)d_in[3];
    const float* b_h1  = (const float*)d_in[4];
    const float* W_h2  = (const float*)d_in[5];
    const float* b_h2  = (const float*)d_in[6];
    const float* W_out = (const float*)d_in[7];
    const float* b_out = (const float*)d_in[8];
    float* out = (float*)d_out;

    f16 *A0, *A1, *s1, *s2, *s3;
    f16 *Wi0, *Wi1, *W10, *W11, *W20, *W21;
    float *cur12, *cur3, *curout;
    cudaGetSymbolAddress((void**)&A0, g_A0);
    cudaGetSymbolAddress((void**)&A1, g_A1);
    cudaGetSymbolAddress((void**)&cur12, g_cur1);
    cudaGetSymbolAddress((void**)&cur3, g_cur3);
    cudaGetSymbolAddress((void**)&curout, g_curout);
    cudaGetSymbolAddress((void**)&s1, g_s1);
    cudaGetSymbolAddress((void**)&s2, g_s2);
    cudaGetSymbolAddress((void**)&s3, g_s3);
    cudaGetSymbolAddress((void**)&Wi0, g_Wi0);
    cudaGetSymbolAddress((void**)&Wi1, g_Wi1);
    cudaGetSymbolAddress((void**)&W10, g_W10);
    cudaGetSymbolAddress((void**)&W11, g_W11);
    cudaGetSymbolAddress((void**)&W20, g_W20);
    cudaGetSymbolAddress((void**)&W21, g_W21);

    // smem: 3 stages * (128 + 64) rows * 72 elems * 2B = 82944
    constexpr int SMEM = 3 * (128 + 64) * 72 * 2;
    auto kfc1 = mma_gemm<3, 1024>;
    auto kfc23 = mma_gemm<2, 512>;
    cudaFuncSetAttribute(kfc1,  cudaFuncAttributeMaxDynamicSharedMemorySize, SMEM);
    cudaFuncSetAttribute(kfc23, cudaFuncAttributeMaxDynamicSharedMemorySize, SMEM);

    wsplit_kernel<<<(H0*INDIM + 255)/256, 256>>>(W_in, H0*INDIM, Wi0, Wi1);
    wsplit_kernel<<<(H1*H0   + 255)/256, 256>>>(W_h1, H1*H0,   W10, W11);
    wsplit_kernel<<<(H2*H1   + 255)/256, 256>>>(W_h2, H2*H1,   W20, W21);

    pool_kernel<<<(MALL*INDIM + 255)/256, 256>>>(x);

    // fc1: 3-term fp16 split GEMM (19968x1024 -> 512), 1248 blocks
    {
        Terms t1;
        t1.A[0]=A0; t1.B[0]=Wi0;
        t1.A[1]=A0; t1.B[1]=Wi1;
        t1.A[2]=A1; t1.B[2]=Wi0;
        kfc1<<<dim3(H0/64, MALL/128), 128, SMEM>>>(t1, b_in, cur12, H0);
    }
    lif_scan_kernel<<<(MROWS*H0/4 + 255)/256, 256>>>(cur12, s1, MROWS*H0, 0.5f);

    // fc2: 2-term spike GEMM (19968x512 -> 512), 1248 blocks
    {
        Terms t2;
        t2.A[0]=s1; t2.B[0]=W10;
        t2.A[1]=s1; t2.B[1]=W11;
        t2.A[2]=s1; t2.B[2]=W10;   // unused (NT=2)
        kfc23<<<dim3(H1/64, MALL/128), 128, SMEM>>>(t2, b_h1, cur12, H1);
    }
    lif_scan_kernel<<<(MROWS*H1/4 + 255)/256, 256>>>(cur12, s2, MROWS*H1, 0.5f);

    // fc3: 2-term spike GEMM (19968x512 -> 256), 624 blocks
    {
        Terms t3;
        t3.A[0]=s2; t3.B[0]=W20;
        t3.A[1]=s2; t3.B[1]=W21;
        t3.A[2]=s2; t3.B[2]=W20;   // unused (NT=2)
        kfc23<<<dim3(H2/64, MALL/128), 128, SMEM>>>(t3, b_h2, cur3, H2);
    }
    lif_scan_kernel<<<(MROWS*H2/4 + 255)/256, 256>>>(cur3, s3, MROWS*H2, 0.5f);

    fcout_kernel<<<TSTEPS*BATCH, 256>>>(s3, W_out, b_out, curout);
    lifout_kernel<<<1, BATCH*NCLS>>>(curout, out);
}

// round 17
// speedup vs baseline: 1.6899x; 1.0571x over previous
#include <cuda_runtime.h>
#include <cuda_fp16.h>
#include <cstdint>
#include <cstddef>

typedef __half f16;

// ---------------- problem constants ----------------
#define TSTEPS 8
#define BATCH  64
#define CC     3
#define NWIN   232
#define HH     64
#define WW     64
#define CHUNK  29
#define DPP    13
#define INDIM  1024
#define H0     512
#define H1     512
#define H2     256
#define CD     39
#define FEAT   9984
#define NCLS   4
#define MROWS  (BATCH*CD)        // 2496
#define MALL   (TSTEPS*MROWS)    // 19968 rows, layout row = (b*CD+cd)*8 + t
#define BETA   0.9f

// ---------------- scratch (static device memory) ----------------
__device__ f16   g_A0[(size_t)MALL * INDIM];
__device__ f16   g_A1[(size_t)MALL * INDIM];
__device__ f16   g_s1[(size_t)MALL * H0];
__device__ f16   g_s2[(size_t)MALL * H1];
__device__ f16   g_s3[(size_t)MALL * H2];
__device__ float g_curout[TSTEPS * BATCH * NCLS];
__device__ f16 g_Wi0[H0 * INDIM], g_Wi1[H0 * INDIM];
__device__ f16 g_W10[H1 * H0],    g_W11[H1 * H0];
__device__ f16 g_W20[H2 * H1],    g_W21[H2 * H1];

// ---------------- fp32 -> 2x fp16 split (24-bit capture) ----------------
__device__ __forceinline__ void split2(float a, f16& h0, f16& h1) {
    h0 = __float2half_rn(a);
    float r = a - __half2float(h0);    // exact (error-free transform)
    h1 = __float2half_rn(r);           // residual <= 2^-24 |a|
}

__global__ void wsplit_kernel(const float* __restrict__ w, int n,
                              f16* __restrict__ h0, f16* __restrict__ h1) {
    int i = blockIdx.x * blockDim.x + threadIdx.x;
    if (i >= n) return;
    f16 a, b;
    split2(w[i], a, b);
    h0[i] = a; h1[i] = b;
}

// ---------------- avg-pool3d fused with A-matrix 2-split ----------------
// A row layout: row = (b*CD + cd)*8 + t  (time-minor for fused LIF epilogue)
__global__ void pool_kernel(const float* __restrict__ x) {
    int idx = blockIdx.x * blockDim.x + threadIdx.x;
    if (idx >= MALL * INDIM) return;
    int hw  = idx & (INDIM - 1);
    int row = idx >> 10;
    int t   = row & 7;
    int rc  = row >> 3;           // b*CD + cd
    int cd  = rc % CD;
    int b   = rc / CD;
    int c   = cd / DPP;
    int dp  = cd % DPP;
    int hp  = hw >> 5;
    int wp  = hw & 31;
    int d0  = t * CHUNK + 2 * dp;
    const float* base = x + (((size_t)b * CC + c) * NWIN) * (HH * WW)
                          + (size_t)(2 * hp) * WW + (size_t)(2 * wp);
    float s = 0.f;
#pragma unroll
    for (int kd = 0; kd < 4; kd++) {
        const float* p = base + (size_t)(d0 + kd) * (HH * WW);
        float2 r0 = *(const float2*)(p);
        float2 r1 = *(const float2*)(p + WW);
        s += (r0.x + r0.y) + (r1.x + r1.y);
    }
    s *= (1.0f / 16.0f);
    f16 h0, h1;
    split2(s, h0, h1);
    g_A0[idx] = h0; g_A1[idx] = h1;
}

// ---------------- cp.async / ldmatrix helpers ----------------
__device__ __forceinline__ void cpasync16(void* s, const void* g) {
    uint32_t sa = (uint32_t)__cvta_generic_to_shared(s);
    asm volatile("cp.async.cg.shared.global [%0], [%1], 16;\n" :: "r"(sa), "l"(g));
}
__device__ __forceinline__ void cp_commit() {
    asm volatile("cp.async.commit_group;\n");
}
template<int N> __device__ __forceinline__ void cp_wait() {
    asm volatile("cp.async.wait_group %0;\n" :: "n"(N));
}
__device__ __forceinline__ void ldmatrix_x4(uint32_t* r, const void* p) {
    uint32_t a = (uint32_t)__cvta_generic_to_shared(p);
    asm volatile("ldmatrix.sync.aligned.m8n8.x4.shared.b16 {%0,%1,%2,%3}, [%4];\n"
        : "=r"(r[0]), "=r"(r[1]), "=r"(r[2]), "=r"(r[3]) : "r"(a));
}

// ---------------- fp16 multi-term GEMM + fused LIF epilogue ---------------
struct Terms {
    const f16* A[3];
    const f16* B[3];
};

__device__ __forceinline__ void mma16816(float* c, const uint32_t* a, const uint32_t* b) {
    asm volatile(
        "mma.sync.aligned.m16n8k16.row.col.f32.f16.f16.f32 "
        "{%0,%1,%2,%3},{%4,%5,%6,%7},{%8,%9},{%0,%1,%2,%3};\n"
        : "+f"(c[0]), "+f"(c[1]), "+f"(c[2]), "+f"(c[3])
        : "r"(a[0]), "r"(a[1]), "r"(a[2]), "r"(a[3]), "r"(b[0]), "r"(b[1]));
}

// BM=128 (16 logical rows x 8 timesteps), BN=64, BK=64, 4 warps, 2 CTAs/SM.
// Epilogue: stage tile+bias in smem, run 8-step LIF per (row,col), write f16 spikes.
template<int NT, int K>
__global__ void __launch_bounds__(128, 2)
mma_gemm_lif(Terms terms, const float* __restrict__ bias,
             f16* __restrict__ spkOut, int N, float thr) {
    constexpr int BM = 128, BN = 64, BK = 64;
    constexpr int WM = 64,  WN = 32;
    constexpr int PAD = 8, LDW = BK + PAD;
    constexpr int STAGES = 3;
    constexpr int KT = K / BK;
    constexpr int NTILE = NT * KT;
    constexpr int MF = WM / 16, NF = WN / 8;   // 4, 4
    constexpr int LDC = BN + 4;                 // fp32 epilogue staging

    extern __shared__ char dynsmem[];
    f16 (*As)[BM][LDW] = (f16(*)[BM][LDW])dynsmem;
    f16 (*Bs)[BN][LDW] = (f16(*)[BN][LDW])(dynsmem + (size_t)STAGES * BM * LDW * 2);
    float (*Cs)[LDC] = (float(*)[LDC])dynsmem;  // aliases stages after drain

    const int tid  = threadIdx.x;
    const int lane = tid & 31;
    const int warp = tid >> 5;
    const int g    = lane >> 2;
    const int tg   = lane & 3;
    const int wn0  = (warp & 1) * WN;
    const int wm0  = (warp >> 1) * WM;
    const int bm   = blockIdx.y * BM;
    const int bn   = blockIdx.x * BN;

    const int l8   = lane & 7;
    const int aRow = ((lane >> 3) & 1) * 8 + l8;
    const int aCol = (lane >> 4) * 8;
    const int bRow = (lane >> 4) * 8 + l8;
    const int bCol = ((lane >> 3) & 1) * 8;

    const int lr = tid >> 3;
    const int lc = (tid & 7) * 8;

    auto load_tile = [&](int i, int s) {
        const int term = i / KT;
        const int k0   = (i % KT) * BK;
        const f16* __restrict__ Ag = terms.A[term] + (size_t)bm * K + k0;
        const f16* __restrict__ Bg = terms.B[term] + (size_t)bn * K + k0;
#pragma unroll
        for (int it = 0; it < BM/16; it++)
            cpasync16(&As[s][lr + it*16][lc], Ag + (size_t)(lr + it*16) * K + lc);
#pragma unroll
        for (int it = 0; it < BN/16; it++)
            cpasync16(&Bs[s][lr + it*16][lc], Bg + (size_t)(lr + it*16) * K + lc);
        cp_commit();
    };

    float acc[MF][NF][4];
#pragma unroll
    for (int i = 0; i < MF; i++)
#pragma unroll
        for (int j = 0; j < NF; j++)
#pragma unroll
            for (int q = 0; q < 4; q++) acc[i][j][q] = 0.f;

#pragma unroll
    for (int i = 0; i < STAGES - 1; i++) load_tile(i, i);

    for (int i = 0; i < NTILE; i++) {
        cp_wait<STAGES - 2>();
        __syncthreads();
        const int nxt = i + STAGES - 1;
        if (nxt < NTILE) load_tile(nxt, nxt % STAGES);
        else cp_commit();              // keep group counting aligned on tail
        const int st = i % STAGES;
#pragma unroll
        for (int ks = 0; ks < BK; ks += 16) {
            uint32_t fa[MF][4], fb[NF][2];
#pragma unroll
            for (int mf = 0; mf < MF; mf++)
                ldmatrix_x4(fa[mf], &As[st][wm0 + mf*16 + aRow][ks + aCol]);
#pragma unroll
            for (int p = 0; p < NF/2; p++) {
                uint32_t r[4];
                ldmatrix_x4(r, &Bs[st][wn0 + p*16 + bRow][ks + bCol]);
                fb[2*p  ][0] = r[0]; fb[2*p  ][1] = r[1];
                fb[2*p+1][0] = r[2]; fb[2*p+1][1] = r[3];
            }
#pragma unroll
            for (int mf = 0; mf < MF; mf++)
#pragma unroll
                for (int nf = 0; nf < NF; nf++)
                    mma16816(acc[mf][nf], fa[mf], fb[nf]);
        }
    }

    // ---- fused LIF epilogue ----
    cp_wait<0>();
    __syncthreads();                    // all reads of As/Bs done; safe to alias
#pragma unroll
    for (int mf = 0; mf < MF; mf++) {
#pragma unroll
        for (int nf = 0; nf < NF; nf++) {
#pragma unroll
            for (int q = 0; q < 4; q++) {
                int ml = wm0 + mf*16 + g + (q >> 1) * 8;
                int nl = wn0 + nf*8 + 2*tg + (q & 1);
                Cs[ml][nl] = acc[mf][nf][q] + bias[bn + nl];
            }
        }
    }
    __syncthreads();
    // scan: 128 threads; thread handles column n for 8 logical rows
    {
        const int n   = tid & 63;
        const int rg0 = (tid >> 6) * 8;   // 0 or 8
#pragma unroll
        for (int k = 0; k < 8; k++) {
            const int rg = rg0 + k;       // logical row within tile (0..15)
            float m = 0.f;
            f16* orow = spkOut + (size_t)(bm + rg*8) * N + bn + n;
#pragma unroll
            for (int t = 0; t < TSTEPS; t++) {
                float reset = (m > thr) ? thr : 0.f;
                m = BETA * m + Cs[rg*8 + t][n] - reset;
                orow[(size_t)t * N] = __float2half_rn((m - thr) > 0.f ? 1.f : 0.f);
            }
        }
    }
}

// ---------------- readout currents: (t,b) row x Wout (4 x 9984) ----------
// s3 layout: row (b*CD+cd)*8 + t, H2 cols -> feature (cd,h) at cd*8*H2 + h
__global__ void fcout_kernel(const f16* __restrict__ s3,
                             const float* __restrict__ Wout,
                             const float* __restrict__ bout,
                             float* __restrict__ curout) {
    const int tb  = blockIdx.x;          // t*BATCH + b
    const int t   = tb / BATCH;
    const int b   = tb % BATCH;
    const int tid = threadIdx.x;         // 256
    const f16* sp = s3 + ((size_t)b * CD * 8 + t) * H2;
    float a0 = 0.f, a1 = 0.f, a2 = 0.f, a3 = 0.f;
    for (int k = tid; k < FEAT; k += 256) {
        int cd = k >> 8;                 // H2 = 256
        int h  = k & 255;
        if (__half2float(sp[(size_t)cd * 8 * H2 + h]) != 0.f) {
            a0 += Wout[0 * FEAT + k];
            a1 += Wout[1 * FEAT + k];
            a2 += Wout[2 * FEAT + k];
            a3 += Wout[3 * FEAT + k];
        }
    }
    __shared__ float red[4][256];
    red[0][tid] = a0; red[1][tid] = a1; red[2][tid] = a2; red[3][tid] = a3;
    __syncthreads();
    for (int st = 128; st > 0; st >>= 1) {
        if (tid < st) {
#pragma unroll
            for (int n = 0; n < 4; n++) red[n][tid] += red[n][tid + st];
        }
        __syncthreads();
    }
    if (tid < NCLS)
        curout[(size_t)tb * NCLS + tid] = red[tid][0] + bout[tid];
}

// ---------------- output LIF scan (thr = 1.0) ----------------------------
__global__ void lifout_kernel(const float* __restrict__ curout,
                              float* __restrict__ out) {
    int i = threadIdx.x;                 // BATCH*NCLS = 256
    float m = 0.f;
#pragma unroll
    for (int t = 0; t < TSTEPS; t++) {
        float reset = (m > 1.0f) ? 1.0f : 0.f;
        m = BETA * m + curout[t * BATCH * NCLS + i] - reset;
        out[t * BATCH * NCLS + i] = (m - 1.0f) > 0.f ? 1.f : 0.f;
    }
}

// ---------------- host orchestration (single stream) ----------------------
extern "C" void kernel_launch(void* const* d_in, const int* in_sizes, int n_in,
                              void* d_out, int out_size) {
    const float* x     = (const float*)d_in[0];
    const float* W_in  = (const float*)d_in[1];
    const float* b_in  = (const float*)d_in[2];
    const float* W_h1  = (const float*)d_in[3];
    const float* b_h1  = (const float*)d_in[4];
    const float* W_h2  = (const float*)d_in[5];
    const float* b_h2  = (const float*)d_in[6];
    const float* W_out = (const float*)d_in[7];
    const float* b_out = (const float*)d_in[8];
    float* out = (float*)d_out;

    f16 *A0, *A1, *s1, *s2, *s3;
    f16 *Wi0, *Wi1, *W10, *W11, *W20, *W21;
    float *curout;
    cudaGetSymbolAddress((void**)&A0, g_A0);
    cudaGetSymbolAddress((void**)&A1, g_A1);
    cudaGetSymbolAddress((void**)&curout, g_curout);
    cudaGetSymbolAddress((void**)&s1, g_s1);
    cudaGetSymbolAddress((void**)&s2, g_s2);
    cudaGetSymbolAddress((void**)&s3, g_s3);
    cudaGetSymbolAddress((void**)&Wi0, g_Wi0);
    cudaGetSymbolAddress((void**)&Wi1, g_Wi1);
    cudaGetSymbolAddress((void**)&W10, g_W10);
    cudaGetSymbolAddress((void**)&W11, g_W11);
    cudaGetSymbolAddress((void**)&W20, g_W20);
    cudaGetSymbolAddress((void**)&W21, g_W21);

    // smem: 3 stages * (128 + 64) rows * 72 elems * 2B = 82944
    constexpr int SMEM = 3 * (128 + 64) * 72 * 2;
    auto kfc1 = mma_gemm_lif<3, 1024>;
    auto kfc23 = mma_gemm_lif<2, 512>;
    cudaFuncSetAttribute(kfc1,  cudaFuncAttributeMaxDynamicSharedMemorySize, SMEM);
    cudaFuncSetAttribute(kfc23, cudaFuncAttributeMaxDynamicSharedMemorySize, SMEM);

    wsplit_kernel<<<(H0*INDIM + 255)/256, 256>>>(W_in, H0*INDIM, Wi0, Wi1);
    wsplit_kernel<<<(H1*H0   + 255)/256, 256>>>(W_h1, H1*H0,   W10, W11);
    wsplit_kernel<<<(H2*H1   + 255)/256, 256>>>(W_h2, H2*H1,   W20, W21);

    pool_kernel<<<(MALL*INDIM + 255)/256, 256>>>(x);

    // fc1 + LIF1 fused: 3-term fp16 split GEMM (19968x1024 -> 512 spikes)
    {
        Terms t1;
        t1.A[0]=A0; t1.B[0]=Wi0;
        t1.A[1]=A0; t1.B[1]=Wi1;
        t1.A[2]=A1; t1.B[2]=Wi0;
        kfc1<<<dim3(H0/64, MALL/128), 128, SMEM>>>(t1, b_in, s1, H0, 0.5f);
    }

    // fc2 + LIF2 fused: 2-term spike GEMM (19968x512 -> 512 spikes)
    {
        Terms t2;
        t2.A[0]=s1; t2.B[0]=W10;
        t2.A[1]=s1; t2.B[1]=W11;
        t2.A[2]=s1; t2.B[2]=W10;   // unused (NT=2)
        kfc23<<<dim3(H1/64, MALL/128), 128, SMEM>>>(t2, b_h1, s2, H1, 0.5f);
    }

    // fc3 + LIF3 fused: 2-term spike GEMM (19968x512 -> 256 spikes)
    {
        Terms t3;
        t3.A[0]=s2; t3.B[0]=W20;
        t3.A[1]=s2; t3.B[1]=W21;
        t3.A[2]=s2; t3.B[2]=W20;   // unused (NT=2)
        kfc23<<<dim3(H2/64, MALL/128), 128, SMEM>>>(t3, b_h2, s3, H2, 0.5f);
    }

    fcout_kernel<<<TSTEPS*BATCH, 256>>>(s3, W_out, b_out, curout);
    lifout_kernel<<<1, BATCH*NCLS>>>(curout, out);
}